// round 4
// baseline (speedup 1.0000x reference)
#include <cuda_runtime.h>
#include <cuda_bf16.h>

#define NN 40000
#define DD 128
#define EE 640000

// ---------------- device scratch (static, no allocation) ----------------
__device__ float g_h  [(size_t)NN * DD];   // h = (1+eps)*x + agg
__device__ float g_h1 [(size_t)NN * DD];   // h @ W1.T + b1
__device__ int   g_csr[EE];
__device__ int   g_cnt[NN];
__device__ int   g_off[NN + 1];
__device__ int   g_cur[NN];
__device__ float g_colsum[DD];
__device__ float g_colsq [DD];
__device__ float g_scale [DD];
__device__ float g_shift [DD];

// ---------------- K0: zero counters + stats ----------------
__global__ void zero_kernel() {
    int i = blockIdx.x * blockDim.x + threadIdx.x;
    if (i < NN) g_cnt[i] = 0;
    if (i < DD) { g_colsum[i] = 0.f; g_colsq[i] = 0.f; }
}

// ---------------- K1: histogram of dst ----------------
__global__ void hist_kernel(const int* __restrict__ dst) {
    int e = blockIdx.x * blockDim.x + threadIdx.x;
    if (e < EE) atomicAdd(&g_cnt[dst[e]], 1);
}

// ---------------- K2: exclusive scan (single block, 1024 threads) ----------------
__global__ void scan_kernel() {
    __shared__ int ssum[1024];
    const int CH = (NN + 1023) / 1024;   // 40
    int t = threadIdx.x;
    int begin = t * CH;
    int end   = begin + CH; if (end > NN) end = NN;
    int s = 0;
    for (int i = begin; i < end; ++i) s += g_cnt[i];
    ssum[t] = s;
    __syncthreads();
    // inclusive Hillis-Steele
    for (int off = 1; off < 1024; off <<= 1) {
        int v = (t >= off) ? ssum[t - off] : 0;
        __syncthreads();
        ssum[t] += v;
        __syncthreads();
    }
    int run = ssum[t] - s;              // exclusive prefix
    for (int i = begin; i < end; ++i) {
        g_off[i] = run;
        g_cur[i] = run;
        run += g_cnt[i];
    }
    if (t == 0) g_off[NN] = EE;
}

// ---------------- K3: scatter edges into CSR ----------------
__global__ void scatter_kernel(const int* __restrict__ src,
                               const int* __restrict__ dst) {
    int e = blockIdx.x * blockDim.x + threadIdx.x;
    if (e < EE) {
        int d = dst[e];
        int p = atomicAdd(&g_cur[d], 1);
        g_csr[p] = src[e];
    }
}

// ---------------- K4: aggregate (one warp per row) + eps residual ----------------
__global__ __launch_bounds__(256)
void agg_kernel(const float* __restrict__ x, const float* __restrict__ eps) {
    int gt   = blockIdx.x * blockDim.x + threadIdx.x;
    int row  = gt >> 5;
    int lane = gt & 31;
    if (row >= NN) return;

    float s0 = 1.0f + eps[0];
    float4 a = *((const float4*)(x + (size_t)row * DD) + lane);
    a.x *= s0; a.y *= s0; a.z *= s0; a.w *= s0;

    int jb = g_off[row], je = g_off[row + 1];
    for (int j0 = jb; j0 < je; j0 += 32) {
        int rem = je - j0;
        int myidx = (lane < rem) ? g_csr[j0 + lane] : 0;
        int cnt = rem < 32 ? rem : 32;
        for (int t = 0; t < cnt; ++t) {
            int sidx = __shfl_sync(0xffffffffu, myidx, t);
            float4 v = *((const float4*)(x + (size_t)sidx * DD) + lane);
            a.x += fmaxf(v.x, 0.f);
            a.y += fmaxf(v.y, 0.f);
            a.z += fmaxf(v.z, 0.f);
            a.w += fmaxf(v.w, 0.f);
        }
    }
    *((float4*)(g_h + (size_t)row * DD) + lane) = a;
}

// ---------------- GEMM: out[r][c] = sum_k A[r][k] * W[c][k] + bias[c] ----------------
// MODE 0: A = g_h (raw), W = W1, bias = b1, out = g_h1, accumulate BN column stats
// MODE 1: A = g_h1 with fused BN-normalize + ReLU on load, W = W2, bias = b2, out = d_out
#define BK 32
#define BMP 132   // padded row length in transposed smem tiles

template <int MODE>
__global__ __launch_bounds__(256)
void gemm_kernel(const float* __restrict__ W,
                 const float* __restrict__ bias,
                 float* __restrict__ out) {
    __shared__ float As[BK][BMP];
    __shared__ float Ws[BK][BMP];
    __shared__ float bsum[DD];
    __shared__ float bsq [DD];

    int tid = threadIdx.x;
    int tx = tid & 15, ty = tid >> 4;
    int r0 = blockIdx.x * 128;

    if (MODE == 0 && tid < DD) { bsum[tid] = 0.f; bsq[tid] = 0.f; }

    const float* A = (MODE == 0) ? g_h : g_h1;

    float acc[8][8];
    #pragma unroll
    for (int i = 0; i < 8; ++i)
        #pragma unroll
        for (int j = 0; j < 8; ++j) acc[i][j] = 0.f;

    for (int k0 = 0; k0 < DD; k0 += BK) {
        // load A tile (128 rows x 32 k) transposed, and W tile (128 c x 32 k) transposed
        #pragma unroll
        for (int it = 0; it < 4; ++it) {
            int slot = it * 256 + tid;       // 0..1023
            int r  = slot >> 3;              // 0..127
            int kq = slot & 7;               // float4 quarter
            int k  = k0 + kq * 4;
            int gr = r0 + r;
            float4 v;
            if (gr < NN) v = *(const float4*)(A + (size_t)gr * DD + k);
            else         v = make_float4(0.f, 0.f, 0.f, 0.f);
            if (MODE == 1) {
                v.x = fmaxf(fmaf(v.x, g_scale[k + 0], g_shift[k + 0]), 0.f);
                v.y = fmaxf(fmaf(v.y, g_scale[k + 1], g_shift[k + 1]), 0.f);
                v.z = fmaxf(fmaf(v.z, g_scale[k + 2], g_shift[k + 2]), 0.f);
                v.w = fmaxf(fmaf(v.w, g_scale[k + 3], g_shift[k + 3]), 0.f);
            }
            As[kq * 4 + 0][r] = v.x;
            As[kq * 4 + 1][r] = v.y;
            As[kq * 4 + 2][r] = v.z;
            As[kq * 4 + 3][r] = v.w;

            float4 wv = *(const float4*)(W + (size_t)r * DD + k);  // r == c index (always < 128)
            Ws[kq * 4 + 0][r] = wv.x;
            Ws[kq * 4 + 1][r] = wv.y;
            Ws[kq * 4 + 2][r] = wv.z;
            Ws[kq * 4 + 3][r] = wv.w;
        }
        __syncthreads();

        #pragma unroll 4
        for (int kk = 0; kk < BK; ++kk) {
            float a[8], b[8];
            *(float4*)(a)     = *(const float4*)(&As[kk][ty * 8]);
            *(float4*)(a + 4) = *(const float4*)(&As[kk][ty * 8 + 4]);
            *(float4*)(b)     = *(const float4*)(&Ws[kk][tx * 8]);
            *(float4*)(b + 4) = *(const float4*)(&Ws[kk][tx * 8 + 4]);
            #pragma unroll
            for (int i = 0; i < 8; ++i)
                #pragma unroll
                for (int j = 0; j < 8; ++j)
                    acc[i][j] = fmaf(a[i], b[j], acc[i][j]);
        }
        __syncthreads();
    }

    // epilogue
    float ps[8], pq[8];
    #pragma unroll
    for (int j = 0; j < 8; ++j) { ps[j] = 0.f; pq[j] = 0.f; }

    #pragma unroll
    for (int i = 0; i < 8; ++i) {
        int r = r0 + ty * 8 + i;
        if (r < NN) {
            #pragma unroll
            for (int j = 0; j < 8; ++j) {
                int c = tx * 8 + j;
                float v = acc[i][j] + bias[c];
                if (MODE == 0) {
                    g_h1[(size_t)r * DD + c] = v;
                    ps[j] += v;
                    pq[j] += v * v;
                } else {
                    out[(size_t)r * DD + c] = v;
                }
            }
        }
    }

    if (MODE == 0) {
        #pragma unroll
        for (int j = 0; j < 8; ++j) {
            atomicAdd(&bsum[tx * 8 + j], ps[j]);
            atomicAdd(&bsq [tx * 8 + j], pq[j]);
        }
        __syncthreads();
        if (tid < DD) {
            atomicAdd(&g_colsum[tid], bsum[tid]);
            atomicAdd(&g_colsq [tid], bsq [tid]);
        }
    }
}

// ---------------- K6: finalize BN scale/shift ----------------
__global__ void finalize_kernel(const float* __restrict__ gamma,
                                const float* __restrict__ beta) {
    int c = threadIdx.x;
    if (c < DD) {
        float invn = 1.0f / (float)NN;
        float mu  = g_colsum[c] * invn;
        float var = g_colsq[c] * invn - mu * mu;
        float sc  = gamma[c] * rsqrtf(var + 1e-5f);
        g_scale[c] = sc;
        g_shift[c] = beta[c] - mu * sc;
    }
}

// ---------------- launch ----------------
extern "C" void kernel_launch(void* const* d_in, const int* in_sizes, int n_in,
                              void* d_out, int out_size) {
    const float* x     = (const float*)d_in[0];
    const int*   src   = (const int*)  d_in[1];   // jax int64 -> int32 (x64 disabled)
    const int*   dst   = (const int*)  d_in[2];
    const float* W1    = (const float*)d_in[3];
    const float* b1    = (const float*)d_in[4];
    const float* gamma = (const float*)d_in[5];
    const float* beta  = (const float*)d_in[6];
    const float* W2    = (const float*)d_in[7];
    const float* b2    = (const float*)d_in[8];
    const float* eps   = (const float*)d_in[9];
    float*       out   = (float*)d_out;

    (void)in_sizes; (void)n_in; (void)out_size;

    zero_kernel   <<<(NN + 255) / 256, 256>>>();
    hist_kernel   <<<(EE + 255) / 256, 256>>>(dst);
    scan_kernel   <<<1, 1024>>>();
    scatter_kernel<<<(EE + 255) / 256, 256>>>(src, dst);
    agg_kernel    <<<(NN * 32 + 255) / 256, 256>>>(x, eps);

    int gblocks = (NN + 127) / 128;   // 313
    gemm_kernel<0><<<gblocks, 256>>>(W1, b1, nullptr);
    finalize_kernel<<<1, 128>>>(gamma, beta);
    gemm_kernel<1><<<gblocks, 256>>>(W2, b2, out);
}